// round 2
// baseline (speedup 1.0000x reference)
#include <cuda_runtime.h>

// Problem constants (static per reference)
#define BSZ   128
#define NTOT  129
#define NPT   128          // N
#define GS    16
#define CH    384          // channels
#define CH4   96           // CH / 4
#define EPSW  0.05f
#define RMSEPS 1e-6f

__global__ __launch_bounds__(128)
void K_Rectify_38216619000515_kernel(
    const float* __restrict__ f,        // (B, NTOT, CH)
    const float* __restrict__ distance, // (B, N, GS)
    const float* __restrict__ rf,       // (NTOT, CH)
    const float* __restrict__ knorm_w,  // (CH,)
    const int*   __restrict__ idx,      // (B, N, GS), int32, values in [0, B*N)
    float*       __restrict__ out)      // (B, NTOT, CH)
{
    const int bn  = blockIdx.x;      // 0 .. B*N-1
    const int b   = bn >> 7;         // N == 128
    const int n   = bn & 127;
    const int tid = threadIdx.x;

    __shared__ float sw[GS];         // raw weights 1/(d+eps)
    __shared__ int   srow[GS];       // gathered row index into f (token rows)
    __shared__ float red[4];

    if (tid < GS) {
        float d = distance[bn * GS + tid];
        sw[tid] = 1.0f / (d + EPSW);
        int r = idx[bn * GS + tid] & (BSZ * NPT - 1);  // mask: crash-proof, no-op for valid data
        int rb = r >> 7;                 // r / N
        int rn = r & 127;                // r % N
        srow[tid] = rb * NTOT + rn + 1;  // corresponding row in f
    }

    // cls token passthrough: out[b,0,:] = f[b,0,:]
    if (n == 0) {
        const float* src = f   + (long long)b * NTOT * CH;
        float*       dst = out + (long long)b * NTOT * CH;
        for (int j = tid; j < CH; j += 128) dst[j] = src[j];
    }
    __syncthreads();

    // every thread computes sum of weights (16 shared broadcast reads, cheap)
    float wsum = 0.0f;
#pragma unroll
    for (int g = 0; g < GS; ++g) wsum += sw[g];
    const float invw = 1.0f / wsum;

    const long long xrow = ((long long)b * NTOT + 1 + n) * CH;

    float4 sf = make_float4(0.f, 0.f, 0.f, 0.f);
    float4 xv = make_float4(0.f, 0.f, 0.f, 0.f);
    float  local = 0.0f;
    const bool active = (tid < CH4);

    if (active) {
        // 16 independent coalesced float4 gathers; full unroll for MLP
#pragma unroll
        for (int g = 0; g < GS; ++g) {
            const float4 v = __ldg(((const float4*)(f + (long long)srow[g] * CH)) + tid);
            const float wg = sw[g];
            sf.x = fmaf(wg, v.x, sf.x);
            sf.y = fmaf(wg, v.y, sf.y);
            sf.z = fmaf(wg, v.z, sf.z);
            sf.w = fmaf(wg, v.w, sf.w);
        }
        xv = __ldg(((const float4*)(f + xrow)) + tid);
        // sf = (sum w*row)/W - x     (valid because reference normalizes w, sum=1)
        sf.x = sf.x * invw - xv.x;
        sf.y = sf.y * invw - xv.y;
        sf.z = sf.z * invw - xv.z;
        sf.w = sf.w * invw - xv.w;
        local = sf.x * sf.x + sf.y * sf.y + sf.z * sf.z + sf.w * sf.w;
    }

    // block reduction of sum(sf^2): warp shuffle + shared across 4 warps
#pragma unroll
    for (int off = 16; off > 0; off >>= 1)
        local += __shfl_down_sync(0xffffffffu, local, off);
    if ((tid & 31) == 0) red[tid >> 5] = local;
    __syncthreads();
    const float total = red[0] + red[1] + red[2] + red[3];

    const float rinv = rsqrtf(total * (1.0f / CH) + RMSEPS);

    if (active) {
        const float4 rv = __ldg(((const float4*)(rf + (long long)(1 + n) * CH)) + tid);
        const float4 kv = __ldg(((const float4*)knorm_w) + tid);
        float4 o;
        o.x = rv.x + xv.x + sf.x * rinv * kv.x;
        o.y = rv.y + xv.y + sf.y * rinv * kv.y;
        o.z = rv.z + xv.z + sf.z * rinv * kv.z;
        o.w = rv.w + xv.w + sf.w * rinv * kv.w;
        ((float4*)(out + xrow))[tid] = o;
    }
}

extern "C" void kernel_launch(void* const* d_in, const int* in_sizes, int n_in,
                              void* d_out, int out_size)
{
    const float* f        = (const float*)d_in[0];
    const float* distance = (const float*)d_in[1];
    const float* rf       = (const float*)d_in[2];
    const float* knorm_w  = (const float*)d_in[3];
    const int*   idx      = (const int*)d_in[4];
    float*       out      = (float*)d_out;

    K_Rectify_38216619000515_kernel<<<BSZ * NPT, 128>>>(
        f, distance, rf, knorm_w, idx, out);
}

// round 3
// speedup vs baseline: 1.0662x; 1.0662x over previous
#include <cuda_runtime.h>

// Problem constants (static per reference)
#define BSZ   128
#define NTOT  129
#define NPT   128          // N
#define GS    16
#define CH    384          // channels
#define CH4   96           // CH / 4
#define EPSW  0.05f
#define RMSEPS 1e-6f

__global__ __launch_bounds__(128, 16)
void K_Rectify_38216619000515_kernel(
    const float* __restrict__ f,        // (B, NTOT, CH)
    const float* __restrict__ distance, // (B, N, GS)
    const float* __restrict__ rf,       // (NTOT, CH)
    const float* __restrict__ knorm_w,  // (CH,)
    const int*   __restrict__ idx,      // (B, N, GS), int32, values in [0, B*N)
    float*       __restrict__ out)      // (B, NTOT, CH)
{
    const int bn  = blockIdx.x;      // 0 .. B*N-1
    const int b   = bn >> 7;         // N == 128
    const int n   = bn & 127;
    const int tid = threadIdx.x;

    __shared__ float sw[GS];         // raw weights 1/(d+eps)
    __shared__ int   soff[GS];       // gathered row offset in float4 units
    __shared__ float red[4];

    if (tid < GS) {
        float d = distance[bn * GS + tid];
        sw[tid] = 1.0f / (d + EPSW);
        int r = idx[bn * GS + tid] & (BSZ * NPT - 1);  // mask: crash-proof, no-op for valid data
        int rb = r >> 7;                  // r / N
        int rn = r & 127;                 // r % N
        soff[tid] = (rb * NTOT + rn + 1) * CH4;  // row offset in float4 units (fits int32)
    }

    // cls token passthrough: out[b,0,:] = f[b,0,:]  (float4 copy, 96 lanes)
    if (n == 0 && tid < CH4) {
        const float4* src = (const float4*)f   + b * (NTOT * CH4);
        float4*       dst = (float4*)out       + b * (NTOT * CH4);
        dst[tid] = src[tid];
    }
    __syncthreads();

    // every thread computes sum of weights (16 shared broadcast reads, cheap)
    float wsum = 0.0f;
#pragma unroll
    for (int g = 0; g < GS; ++g) wsum += sw[g];
    const float invw = 1.0f / wsum;

    const int xrow4 = (b * NTOT + 1 + n) * CH4;   // x row offset in float4 units

    float4 sf = make_float4(0.f, 0.f, 0.f, 0.f);
    float4 xv = make_float4(0.f, 0.f, 0.f, 0.f);
    float  local = 0.0f;
    const bool active = (tid < CH4);

    const float4* f4 = (const float4*)f;

    if (active) {
        // 16 independent coalesced float4 gathers; full unroll for MLP
#pragma unroll
        for (int g = 0; g < GS; ++g) {
            const float4 v = __ldg(f4 + soff[g] + tid);
            const float wg = sw[g];
            sf.x = fmaf(wg, v.x, sf.x);
            sf.y = fmaf(wg, v.y, sf.y);
            sf.z = fmaf(wg, v.z, sf.z);
            sf.w = fmaf(wg, v.w, sf.w);
        }
        xv = __ldg(f4 + xrow4 + tid);
        // sf = (sum w*row)/W - x     (valid because reference normalizes w, sum=1)
        sf.x = sf.x * invw - xv.x;
        sf.y = sf.y * invw - xv.y;
        sf.z = sf.z * invw - xv.z;
        sf.w = sf.w * invw - xv.w;
        local = sf.x * sf.x + sf.y * sf.y + sf.z * sf.z + sf.w * sf.w;
    }

    // block reduction of sum(sf^2): warp shuffle + shared across 4 warps
#pragma unroll
    for (int off = 16; off > 0; off >>= 1)
        local += __shfl_down_sync(0xffffffffu, local, off);
    if ((tid & 31) == 0) red[tid >> 5] = local;
    __syncthreads();
    const float total = red[0] + red[1] + red[2] + red[3];

    const float rinv = rsqrtf(total * (1.0f / CH) + RMSEPS);

    if (active) {
        const float4 rv = __ldg((const float4*)rf + (1 + n) * CH4 + tid);
        const float4 kv = __ldg((const float4*)knorm_w + tid);
        float4 o;
        o.x = rv.x + xv.x + sf.x * rinv * kv.x;
        o.y = rv.y + xv.y + sf.y * rinv * kv.y;
        o.z = rv.z + xv.z + sf.z * rinv * kv.z;
        o.w = rv.w + xv.w + sf.w * rinv * kv.w;
        ((float4*)out)[xrow4 + tid] = o;
    }
}

extern "C" void kernel_launch(void* const* d_in, const int* in_sizes, int n_in,
                              void* d_out, int out_size)
{
    const float* f        = (const float*)d_in[0];
    const float* distance = (const float*)d_in[1];
    const float* rf       = (const float*)d_in[2];
    const float* knorm_w  = (const float*)d_in[3];
    const int*   idx      = (const int*)d_in[4];
    float*       out      = (float*)d_out;

    K_Rectify_38216619000515_kernel<<<BSZ * NPT, 128>>>(
        f, distance, rf, knorm_w, idx, out);
}